// round 15
// baseline (speedup 1.0000x reference)
#include <cuda_runtime.h>

#define B_   256
#define C_   3
#define H_   224
#define W_   224
#define HW_  (H_ * W_)          // 50176
#define HW4  (HW_ / 4)          // 12544 float4 per plane
#define NSL  49                 // slices per image (CTAs in x)

#define GW0 0.2989f
#define GW1 0.587f
#define GW2 0.114f

// Deterministic scratch. g_cnt is MONOTONIC across graph replays: each CTA
// derives its epoch target from the atomicAdd return value, so no reset
// kernel is needed (replays are serialized by the harness).
__device__ float g_part[B_ * NSL * 3];
__device__ int   g_cnt[B_];

// ---------------------------------------------------------------------------
// Single fused kernel, 128 threads x 2 pixels (fine residency quantum: ~16
// CTAs/SM so a spinning CTA idles only 1/16 of an SM). Each CTA: load its
// slice once into registers (MLP=6), post per-channel partials, then
//  - non-contrast image: finalize clip(aug(x)*br), exit (never waits).
//  - contrast image: tid0 spins until all 49 slices posted, cooperative
//    deterministic mean reduction, affine transform, store.
// Input read exactly once: DRAM traffic = 154R + 154W = 308 MB (minimum).
// ---------------------------------------------------------------------------
__global__ __launch_bounds__(128) void fused_aug_kernel(
    const float* __restrict__ x,
    const float* __restrict__ brightness,
    const float* __restrict__ contrast_factor,
    const int*   __restrict__ flip_mask,
    const int*   __restrict__ gray_mask,
    const int*   __restrict__ contrast_apply,
    float*       __restrict__ out)
{
    const int b   = blockIdx.y;
    const int sl  = blockIdx.x;
    const int tid = threadIdx.x;
    const int p0  = sl * 256 + tid;                      // pixel A (float4 idx)
    const int p1  = p0 + 128;                            // pixel B

    const float br   = brightness[b];
    const bool  flip = flip_mask[b] != 0;
    const bool  gray = gray_mask[b] != 0;
    const bool  ctr  = contrast_apply[b] != 0;
    const float cf   = ctr ? contrast_factor[b] : 1.0f;

    // flip-aware sources (sum is flip-invariant)
    const int pixA = p0 * 4, hA = pixA / W_, wA = pixA - hA * W_;
    const int pixB = p1 * 4, hB = pixB / W_, wB = pixB - hB * W_;
    const int spA  = flip ? ((hA * W_ + (W_ - 4 - wA)) >> 2) : p0;
    const int spB  = flip ? ((hB * W_ + (W_ - 4 - wB)) >> 2) : p1;

    const float4* __restrict__ in4 =
        reinterpret_cast<const float4*>(x) + (size_t)b * 3 * HW4;
    // 6 independent evict-first loads in flight
    float4 a0 = __ldcs(&in4[0 * HW4 + spA]);
    float4 a1 = __ldcs(&in4[1 * HW4 + spA]);
    float4 a2 = __ldcs(&in4[2 * HW4 + spA]);
    float4 b0 = __ldcs(&in4[0 * HW4 + spB]);
    float4 b1 = __ldcs(&in4[1 * HW4 + spB]);
    float4 b2 = __ldcs(&in4[2 * HW4 + spB]);

    // ---- per-channel partial sums of ORIGINAL x (both pixels) ----
    float s0 = (a0.x + a0.y) + (a0.z + a0.w) + (b0.x + b0.y) + (b0.z + b0.w);
    float s1 = (a1.x + a1.y) + (a1.z + a1.w) + (b1.x + b1.y) + (b1.z + b1.w);
    float s2 = (a2.x + a2.y) + (a2.z + a2.w) + (b2.x + b2.y) + (b2.z + b2.w);
    #pragma unroll
    for (int o = 16; o; o >>= 1) {
        s0 += __shfl_xor_sync(~0u, s0, o);
        s1 += __shfl_xor_sync(~0u, s1, o);
        s2 += __shfl_xor_sync(~0u, s2, o);
    }
    __shared__ float red[3][4];
    if ((tid & 31) == 0) {
        red[0][tid >> 5] = s0; red[1][tid >> 5] = s1; red[2][tid >> 5] = s2;
    }
    __syncthreads();

    // ---- post partials, bump arrival counter, (contrast) spin ----
    if (tid == 0) {
        float q0 = red[0][0] + red[0][1] + red[0][2] + red[0][3];
        float q1 = red[1][0] + red[1][1] + red[1][2] + red[1][3];
        float q2 = red[2][0] + red[2][1] + red[2][2] + red[2][3];
        const int off = (b * NSL + sl) * 3;
        g_part[off + 0] = q0; g_part[off + 1] = q1; g_part[off + 2] = q2;
        __threadfence();                                 // partials before count
        const int old    = atomicAdd(&g_cnt[b], 1);
        const int target = old - (old % NSL) + NSL;      // end of THIS epoch
        if (ctr) {
            volatile int* c = &g_cnt[b];
            while (*c < target) __nanosleep(64);
        }
    }
    __syncthreads();

    float4* __restrict__ out4 =
        reinterpret_cast<float4*>(out) + (size_t)b * 3 * HW4;

    #define REV(v) { float t;                                                \
        t = v.x; v.x = v.w; v.w = t;  t = v.y; v.y = v.z; v.z = t; }
    #define GRAYIFY(c0, c1, c2) {                                            \
        float4 g;                                                            \
        g.x = GW0*c0.x + GW1*c1.x + GW2*c2.x;                                \
        g.y = GW0*c0.y + GW1*c1.y + GW2*c2.y;                                \
        g.z = GW0*c0.z + GW1*c1.z + GW2*c2.z;                                \
        g.w = GW0*c0.w + GW1*c1.w + GW2*c2.w;                                \
        c0 = g; c1 = g; c2 = g; }

    if (!ctr) {
        // ---- no-contrast: out = clip(aug(x)*br) ----
        if (flip) { REV(a0) REV(a1) REV(a2) REV(b0) REV(b1) REV(b2) }
        if (gray) { GRAYIFY(a0, a1, a2) GRAYIFY(b0, b1, b2) }
        #define XFB(v)                                                       \
            v.x = fminf(fmaxf(v.x * br, -2.5f), 2.5f);                       \
            v.y = fminf(fmaxf(v.y * br, -2.5f), 2.5f);                       \
            v.z = fminf(fmaxf(v.z * br, -2.5f), 2.5f);                       \
            v.w = fminf(fmaxf(v.w * br, -2.5f), 2.5f);
        XFB(a0) XFB(a1) XFB(a2) XFB(b0) XFB(b1) XFB(b2)
        #undef XFB
        __stcs(&out4[0 * HW4 + p0], a0);
        __stcs(&out4[1 * HW4 + p0], a1);
        __stcs(&out4[2 * HW4 + p0], a2);
        __stcs(&out4[0 * HW4 + p1], b0);
        __stcs(&out4[1 * HW4 + p1], b1);
        __stcs(&out4[2 * HW4 + p1], b2);
        return;
    }

    // ---- contrast path: cooperative deterministic mean reduction ----
    __shared__ float sm_mean[3];
    if (tid < 96) {
        const int c    = tid >> 5;
        const int lane = tid & 31;
        float s = 0.f;
        if (lane < NSL)      s  = __ldcg(&g_part[(b * NSL + lane) * 3 + c]);
        if (lane + 32 < NSL) s += __ldcg(&g_part[(b * NSL + lane + 32) * 3 + c]);
        #pragma unroll
        for (int o = 16; o; o >>= 1)
            s += __shfl_xor_sync(~0u, s, o);
        if (lane == 0)
            sm_mean[c] = s * (1.0f / (float)HW_);
    }
    __syncthreads();

    const float m0 = sm_mean[0];
    const float m1 = sm_mean[1];
    const float m2 = sm_mean[2];
    const float gm = GW0 * m0 + GW1 * m1 + GW2 * m2;

    const float mm0 = (gray ? gm : m0) * br;
    const float mm1 = (gray ? gm : m1) * br;
    const float mm2 = (gray ? gm : m2) * br;

    const float scale = br * cf;
    const float omcf  = 1.0f - cf;
    const float off0 = mm0 * omcf;
    const float off1 = mm1 * omcf;
    const float off2 = mm2 * omcf;

    if (flip) { REV(a0) REV(a1) REV(a2) REV(b0) REV(b1) REV(b2) }
    if (gray) { GRAYIFY(a0, a1, a2) GRAYIFY(b0, b1, b2) }
    #undef REV
    #undef GRAYIFY

    #define XFORM(v, off)                                                    \
        v.x = fminf(fmaxf(fmaf(v.x, scale, off), -2.5f), 2.5f);             \
        v.y = fminf(fmaxf(fmaf(v.y, scale, off), -2.5f), 2.5f);             \
        v.z = fminf(fmaxf(fmaf(v.z, scale, off), -2.5f), 2.5f);             \
        v.w = fminf(fmaxf(fmaf(v.w, scale, off), -2.5f), 2.5f);
    XFORM(a0, off0) XFORM(a1, off1) XFORM(a2, off2)
    XFORM(b0, off0) XFORM(b1, off1) XFORM(b2, off2)
    #undef XFORM

    __stcs(&out4[0 * HW4 + p0], a0);
    __stcs(&out4[1 * HW4 + p0], a1);
    __stcs(&out4[2 * HW4 + p0], a2);
    __stcs(&out4[0 * HW4 + p1], b0);
    __stcs(&out4[1 * HW4 + p1], b1);
    __stcs(&out4[2 * HW4 + p1], b2);
}

extern "C" void kernel_launch(void* const* d_in, const int* in_sizes, int n_in,
                              void* d_out, int out_size) {
    const float* x   = (const float*)d_in[0];
    const float* br  = (const float*)d_in[1];
    const float* cfv = (const float*)d_in[2];
    const int*   fm  = (const int*)d_in[3];
    const int*   gm  = (const int*)d_in[4];
    const int*   ca  = (const int*)d_in[5];
    float* out = (float*)d_out;

    dim3 grid(NSL, B_);                                  // (49, 256)
    fused_aug_kernel<<<grid, 128>>>(x, br, cfv, fm, gm, ca, out);
}